// round 2
// baseline (speedup 1.0000x reference)
#include <cuda_runtime.h>
#include <cfloat>
#include <cstdint>

#define D        512
#define KCB      1024
#define BM       128
#define BN       128
#define BK       16
#define TM       8
#define NTHREADS 256
#define NCHUNKS  (KCB / BN)   // 8
#define KITERS   (D / BK)     // 32
#define NROWS    65536
#define TAU      0.02f
#define CAP      65536

// Device scratch (no cudaMalloc allowed).
__device__ float g_c2[KCB];
__device__ int   g_best[NROWS];
__device__ int   g_flag_rows[CAP];
__device__ int   g_flag_count;

// ---------- packed f32x2 helpers (sm_100+: FFMA2 path) ----------
__device__ __forceinline__ unsigned long long pack2(float lo, float hi) {
    unsigned long long r;
    asm("mov.b64 %0, {%1, %2};" : "=l"(r) : "f"(lo), "f"(hi));
    return r;
}
__device__ __forceinline__ void unpack2(unsigned long long v, float& lo, float& hi) {
    asm("mov.b64 {%0, %1}, %2;" : "=f"(lo), "=f"(hi) : "l"(v));
}
__device__ __forceinline__ void ffma2(unsigned long long& d, unsigned long long a, unsigned long long b) {
    asm("fma.rn.f32x2 %0, %1, %2, %0;" : "+l"(d) : "l"(a), "l"(b));
}

// ---------- pass 0: ||c||^2 per codeword + reset flag counter ----------
__global__ void c2_kernel(const float* __restrict__ cb) {
    if (blockIdx.x == 0 && threadIdx.x == 0) g_flag_count = 0;
    int cw   = blockIdx.x * (blockDim.x >> 5) + (threadIdx.x >> 5);
    int lane = threadIdx.x & 31;
    const float4* p = reinterpret_cast<const float4*>(cb + (size_t)cw * D);
    float s = 0.f;
    #pragma unroll
    for (int t = lane; t < D / 4; t += 32) {
        float4 v = p[t];
        s += v.x * v.x + v.y * v.y + v.z * v.z + v.w * v.w;
    }
    #pragma unroll
    for (int o = 16; o; o >>= 1) s += __shfl_xor_sync(0xffffffffu, s, o);
    if (lane == 0) g_c2[cw] = s;
}

// ---------- pass 1: fused SGEMM screen + top-2 argmin + flag near-ties ----------
__global__ __launch_bounds__(NTHREADS) void vq_kernel(
    const float* __restrict__ x,
    const float* __restrict__ cb)
{
    __shared__ float As[BK][BM + 4];
    __shared__ float Bs[BK][BN + 4];
    __shared__ float s_c2[BN];
    __shared__ float rv[BM][16];
    __shared__ int   ri[BM][16];
    __shared__ float rs[BM][16];

    const int tid = threadIdx.x;
    const int tx  = tid & 15;   // 16 col-groups
    const int ty  = tid >> 4;   // 16 row-groups
    const int rowbase = blockIdx.x * BM;

    const float* xblk = x + (size_t)rowbase * D;

    float bestv[TM], secondv[TM];
    int   besti[TM];
    #pragma unroll
    for (int i = 0; i < TM; ++i) { bestv[i] = FLT_MAX; secondv[i] = FLT_MAX; besti[i] = 0; }

    for (int chunk = 0; chunk < NCHUNKS; ++chunk) {
        if (tid < BN) s_c2[tid] = g_c2[chunk * BN + tid];
        const float* cblk = cb + (size_t)(chunk * BN) * D;

        unsigned long long acc[TM][4];
        #pragma unroll
        for (int i = 0; i < TM; ++i)
            #pragma unroll
            for (int jp = 0; jp < 4; ++jp) acc[i][jp] = 0ull;

        for (int kt = 0; kt < KITERS; ++kt) {
            const int k0 = kt * BK;
            #pragma unroll
            for (int t = 0; t < 2; ++t) {
                int idx = tid + t * NTHREADS;      // 0..511
                int r   = idx >> 2;                // row within tile
                int kk4 = (idx & 3) << 2;          // k offset (x4)
                float4 va = *reinterpret_cast<const float4*>(xblk + (size_t)r * D + k0 + kk4);
                As[kk4 + 0][r] = va.x; As[kk4 + 1][r] = va.y;
                As[kk4 + 2][r] = va.z; As[kk4 + 3][r] = va.w;
                float4 vb = *reinterpret_cast<const float4*>(cblk + (size_t)r * D + k0 + kk4);
                Bs[kk4 + 0][r] = vb.x; Bs[kk4 + 1][r] = vb.y;
                Bs[kk4 + 2][r] = vb.z; Bs[kk4 + 3][r] = vb.w;
            }
            __syncthreads();

            #pragma unroll
            for (int kk = 0; kk < BK; ++kk) {
                float4 alo = *reinterpret_cast<const float4*>(&As[kk][ty * TM]);
                float4 ahi = *reinterpret_cast<const float4*>(&As[kk][ty * TM + 4]);
                unsigned long long aa[TM];
                aa[0] = pack2(alo.x, alo.x); aa[1] = pack2(alo.y, alo.y);
                aa[2] = pack2(alo.z, alo.z); aa[3] = pack2(alo.w, alo.w);
                aa[4] = pack2(ahi.x, ahi.x); aa[5] = pack2(ahi.y, ahi.y);
                aa[6] = pack2(ahi.z, ahi.z); aa[7] = pack2(ahi.w, ahi.w);

                unsigned long long bb[4];
                #pragma unroll
                for (int jp = 0; jp < 4; ++jp) {
                    float2 bv2 = *reinterpret_cast<const float2*>(&Bs[kk][jp * 32 + tx * 2]);
                    bb[jp] = pack2(bv2.x, bv2.y);
                }
                #pragma unroll
                for (int i = 0; i < TM; ++i)
                    #pragma unroll
                    for (int jp = 0; jp < 4; ++jp)
                        ffma2(acc[i][jp], aa[i], bb[jp]);
            }
            __syncthreads();
        }

        // scores: ||c||^2 - 2 x.c ; top-2 tracking (first-occurrence ties)
        const int colbase = chunk * BN;
        #pragma unroll
        for (int i = 0; i < TM; ++i) {
            #pragma unroll
            for (int jp = 0; jp < 4; ++jp) {   // jp ascending -> cols ascending
                float d0, d1;
                unpack2(acc[i][jp], d0, d1);
                int c0 = jp * 32 + tx * 2;
                float s0 = fmaf(-2.f, d0, s_c2[c0]);
                float s1 = fmaf(-2.f, d1, s_c2[c0 + 1]);
                if (s0 < bestv[i]) { secondv[i] = bestv[i]; bestv[i] = s0; besti[i] = colbase + c0; }
                else if (s0 < secondv[i]) secondv[i] = s0;
                if (s1 < bestv[i]) { secondv[i] = bestv[i]; bestv[i] = s1; besti[i] = colbase + c0 + 1; }
                else if (s1 < secondv[i]) secondv[i] = s1;
            }
        }
        __syncthreads();
    }

    // cross-thread top-2 reduction per row
    #pragma unroll
    for (int i = 0; i < TM; ++i) {
        rv[ty * TM + i][tx] = bestv[i];
        ri[ty * TM + i][tx] = besti[i];
        rs[ty * TM + i][tx] = secondv[i];
    }
    __syncthreads();
    if (tid < BM) {
        float bv = rv[tid][0];
        int   bi = ri[tid][0];
        int   tw = 0;
        #pragma unroll
        for (int t = 1; t < 16; ++t) {
            float v = rv[tid][t];
            int   ix = ri[tid][t];
            if (v < bv || (v == bv && ix < bi)) { bv = v; bi = ix; tw = t; }
        }
        float sv = FLT_MAX;
        #pragma unroll
        for (int t = 0; t < 16; ++t) {
            float cand = (t == tw) ? rs[tid][t] : rv[tid][t];
            if (cand < sv) sv = cand;
        }
        int row = rowbase + tid;
        g_best[row] = bi;
        if (sv - bv < TAU) {
            int slot = atomicAdd(&g_flag_count, 1);
            if (slot < CAP) g_flag_rows[slot] = row;
        }
    }
}

// ---------- pass 2: fp64 rescue of flagged rows (mimic reference fp32 grid) ----------
__global__ __launch_bounds__(256) void rescue_kernel(
    const float* __restrict__ x,
    const float* __restrict__ cb)
{
    __shared__ float sx[D];
    __shared__ float wv[8];
    __shared__ int   wi[8];

    const int tid  = threadIdx.x;
    const int wid  = tid >> 5;
    const int lane = tid & 31;
    int total = g_flag_count;
    if (total > CAP) total = CAP;

    for (int f = blockIdx.x; f < total; f += gridDim.x) {
        const int row = g_flag_rows[f];
        for (int i = tid; i < D; i += 256) sx[i] = x[(size_t)row * D + i];
        __syncthreads();

        // x2 in fp64 (each warp computes redundantly)
        double x2 = 0.0;
        for (int e = lane; e < D; e += 32) { double v = (double)sx[e]; x2 += v * v; }
        #pragma unroll
        for (int o = 16; o; o >>= 1) x2 += __shfl_xor_sync(0xffffffffu, x2, o);
        const float x2f = (float)x2;

        float bv = FLT_MAX;
        int   bi = 1 << 30;
        for (int cw = wid; cw < KCB; cw += 8) {
            const float* c = cb + (size_t)cw * D;
            double dot = 0.0, cc = 0.0;
            for (int e = lane; e < D; e += 32) {
                double cv = (double)c[e];
                dot += (double)sx[e] * cv;
                cc  += cv * cv;
            }
            #pragma unroll
            for (int o = 16; o; o >>= 1) {
                dot += __shfl_xor_sync(0xffffffffu, dot, o);
                cc  += __shfl_xor_sync(0xffffffffu, cc, o);
            }
            // mimic reference fp32 rounding: (x2 - 2*xc) + c2
            float d2 = (x2f - 2.0f * (float)dot) + (float)cc;
            if (d2 < bv) { bv = d2; bi = cw; }   // cw ascending per warp
        }
        if (lane == 0) { wv[wid] = bv; wi[wid] = bi; }
        __syncthreads();
        if (tid == 0) {
            float fbv = wv[0]; int fbi = wi[0];
            #pragma unroll
            for (int t = 1; t < 8; ++t) {
                if (wv[t] < fbv || (wv[t] == fbv && wi[t] < fbi)) { fbv = wv[t]; fbi = wi[t]; }
            }
            g_best[row] = fbi;
        }
        __syncthreads();
    }
}

// ---------- pass 3: gather ----------
__global__ __launch_bounds__(128) void gather_kernel(
    const float* __restrict__ cb,
    float* __restrict__ out)
{
    const int row = blockIdx.x;
    const int bi  = g_best[row];
    const float4* src = reinterpret_cast<const float4*>(cb + (size_t)bi * D);
    float4* dst = reinterpret_cast<float4*>(out + (size_t)row * D);
    dst[threadIdx.x] = src[threadIdx.x];
}

extern "C" void kernel_launch(void* const* d_in, const int* in_sizes, int n_in,
                              void* d_out, int out_size) {
    const float* x  = (const float*)d_in[0];   // [8*8192, 512]
    const float* cb = (const float*)d_in[1];   // [1024, 512]
    float* out = (float*)d_out;
    int nrows = in_sizes[0] / D;               // 65536

    c2_kernel<<<KCB / 8, 256>>>(cb);
    vq_kernel<<<nrows / BM, NTHREADS>>>(x, cb);
    rescue_kernel<<<296, 256>>>(x, cb);
    gather_kernel<<<nrows, 128>>>(cb, out);
}

// round 5
// speedup vs baseline: 3.1429x; 3.1429x over previous
#include <cuda_runtime.h>
#include <cuda_bf16.h>
#include <cfloat>
#include <cstdint>

#define D        512
#define KCB      1024
#define NROWS    65536
#define TAU      0.01f
#define CAP      65536

#define BM       128            // rows per CTA
#define BN       256            // codewords per phase
#define NPH      4              // 1024 / 256
#define KC       64             // K elems per stage
#define NTERM    3              // hi*hi, hi*lo, lo*hi
#define STG_PER_PH (NTERM * (D / KC))   // 24
#define NSTG     (NPH * STG_PER_PH)     // 96
#define NTH      256

// smem layout (bytes)
#define SM_C2    0               // float[1024]
#define SM_PBV   4096            // float[256]
#define SM_PSV   5120            // float[256]
#define SM_PBI   6144            // int[256]
#define SM_BUF   8192            // 2 x 55296
#define STRIDE_B 144             // padded row stride (72 bf16) - conflict free
#define A_BYTES  (BM * STRIDE_B)         // 18432
#define B_BYTES  (BN * STRIDE_B)         // 36864
#define BUF_BYTES (A_BYTES + B_BYTES)    // 55296
#define SM_TOTAL (SM_BUF + 2 * BUF_BYTES) // 118784

// ---- device scratch (no cudaMalloc allowed) ----
__device__ __nv_bfloat16 g_xhi[(size_t)NROWS * D];   // 64 MB
__device__ __nv_bfloat16 g_xlo[(size_t)NROWS * D];   // 64 MB
__device__ __nv_bfloat16 g_cbhi[KCB * D];            // 1 MB
__device__ __nv_bfloat16 g_cblo[KCB * D];            // 1 MB
__device__ float g_c2[KCB];
__device__ int   g_best[NROWS];
__device__ int   g_flag_rows[CAP];
__device__ int   g_flag_count;

// ================= PTX helpers (all baseline sm_80 features) =================
__device__ __forceinline__ uint32_t smem_u32(const void* p) {
    uint32_t a;
    asm("{ .reg .u64 t; cvta.to.shared.u64 t, %1; cvt.u32.u64 %0, t; }" : "=r"(a) : "l"(p));
    return a;
}
#define CP16(s, g)   asm volatile("cp.async.ca.shared.global [%0], [%1], 16;" :: "r"(s), "l"(g))
#define CPCOMMIT()   asm volatile("cp.async.commit_group;")
#define CPWAIT1()    asm volatile("cp.async.wait_group 1;")
#define CPWAIT0()    asm volatile("cp.async.wait_group 0;")
#define LDSM4(r0, r1, r2, r3, a) \
    asm volatile("ldmatrix.sync.aligned.m8n8.x4.shared.b16 {%0,%1,%2,%3}, [%4];" \
                 : "=r"(r0), "=r"(r1), "=r"(r2), "=r"(r3) : "r"(a))

__device__ __forceinline__ void mma_bf16(float* c, const uint32_t* a, uint32_t b0, uint32_t b1) {
    asm volatile(
        "mma.sync.aligned.m16n8k16.row.col.f32.bf16.bf16.f32 "
        "{%0,%1,%2,%3}, {%4,%5,%6,%7}, {%8,%9}, {%0,%1,%2,%3};"
        : "+f"(c[0]), "+f"(c[1]), "+f"(c[2]), "+f"(c[3])
        : "r"(a[0]), "r"(a[1]), "r"(a[2]), "r"(a[3]), "r"(b0), "r"(b1));
}

// ================= prep: split f32 -> bf16 hi/lo =================
__global__ __launch_bounds__(512) void prep_x(const float* __restrict__ x) {
    size_t i = (size_t)blockIdx.x * 512 + threadIdx.x;     // over float4s
    float4 v = reinterpret_cast<const float4*>(x)[i];
    __nv_bfloat162 h01 = __floats2bfloat162_rn(v.x, v.y);
    __nv_bfloat162 h23 = __floats2bfloat162_rn(v.z, v.w);
    __nv_bfloat162 l01 = __floats2bfloat162_rn(v.x - __bfloat162float(h01.x),
                                               v.y - __bfloat162float(h01.y));
    __nv_bfloat162 l23 = __floats2bfloat162_rn(v.z - __bfloat162float(h23.x),
                                               v.w - __bfloat162float(h23.y));
    uint2 hw, lw;
    hw.x = *reinterpret_cast<uint32_t*>(&h01); hw.y = *reinterpret_cast<uint32_t*>(&h23);
    lw.x = *reinterpret_cast<uint32_t*>(&l01); lw.y = *reinterpret_cast<uint32_t*>(&l23);
    reinterpret_cast<uint2*>(g_xhi)[i] = hw;
    reinterpret_cast<uint2*>(g_xlo)[i] = lw;
}
__global__ __launch_bounds__(512) void prep_cb(const float* __restrict__ cb) {
    size_t i = (size_t)blockIdx.x * 512 + threadIdx.x;
    float4 v = reinterpret_cast<const float4*>(cb)[i];
    __nv_bfloat162 h01 = __floats2bfloat162_rn(v.x, v.y);
    __nv_bfloat162 h23 = __floats2bfloat162_rn(v.z, v.w);
    __nv_bfloat162 l01 = __floats2bfloat162_rn(v.x - __bfloat162float(h01.x),
                                               v.y - __bfloat162float(h01.y));
    __nv_bfloat162 l23 = __floats2bfloat162_rn(v.z - __bfloat162float(h23.x),
                                               v.w - __bfloat162float(h23.y));
    uint2 hw, lw;
    hw.x = *reinterpret_cast<uint32_t*>(&h01); hw.y = *reinterpret_cast<uint32_t*>(&h23);
    lw.x = *reinterpret_cast<uint32_t*>(&l01); lw.y = *reinterpret_cast<uint32_t*>(&l23);
    reinterpret_cast<uint2*>(g_cbhi)[i] = hw;
    reinterpret_cast<uint2*>(g_cblo)[i] = lw;
}

// ================= pass 0: ||c||^2 (fp64 accum) + reset flags =================
__global__ void c2_kernel(const float* __restrict__ cb) {
    if (blockIdx.x == 0 && threadIdx.x == 0) g_flag_count = 0;
    int cw   = blockIdx.x * (blockDim.x >> 5) + (threadIdx.x >> 5);
    int lane = threadIdx.x & 31;
    const float4* p = reinterpret_cast<const float4*>(cb + (size_t)cw * D);
    double s = 0.0;
    for (int t = lane; t < D / 4; t += 32) {
        float4 v = p[t];
        s += (double)v.x * v.x + (double)v.y * v.y + (double)v.z * v.z + (double)v.w * v.w;
    }
    #pragma unroll
    for (int o = 16; o; o >>= 1) s += __shfl_xor_sync(0xffffffffu, s, o);
    if (lane == 0) g_c2[cw] = (float)s;
}

// ================= pass 1: bf16-split HMMA screen =================
__device__ __forceinline__ void stage_load(int s, int rowbase, uint32_t sbase, int tid) {
    const int ph = s / STG_PER_PH;
    const int r  = s % STG_PER_PH;
    const int t  = r >> 3;
    const int k0 = (r & 7) * KC;
    const __nv_bfloat16* asrc = (t == 2) ? g_xlo : g_xhi;
    const __nv_bfloat16* bsrc = (t == 1) ? g_cblo : g_cbhi;
    const uint32_t bufo = sbase + SM_BUF + (uint32_t)(s & 1) * BUF_BYTES;
    #pragma unroll
    for (int i = 0; i < 4; ++i) {                 // A: 128 rows x 8 chunks
        int id = tid + i * NTH;
        int row = id >> 3, kc = id & 7;
        CP16(bufo + row * STRIDE_B + kc * 16,
             asrc + (size_t)(rowbase + row) * D + k0 + kc * 8);
    }
    #pragma unroll
    for (int i = 0; i < 8; ++i) {                 // B: 256 rows x 8 chunks
        int id = tid + i * NTH;
        int n = id >> 3, kc = id & 7;
        CP16(bufo + A_BYTES + n * STRIDE_B + kc * 16,
             bsrc + (size_t)(ph * BN + n) * D + k0 + kc * 8);
    }
    CPCOMMIT();
}

__global__ __launch_bounds__(NTH, 1) void vq_mma_kernel() {
    extern __shared__ char smem[];
    const uint32_t sbase = smem_u32(smem);
    const int tid   = threadIdx.x;
    const int lane  = tid & 31;
    const int wid   = tid >> 5;
    const int mwarp = wid >> 1;       // 0..3 -> 32 rows each
    const int nwarp = wid & 1;        // 0..1 -> 128 cols each
    const int rowbase = blockIdx.x * BM;

    float* s_c2  = reinterpret_cast<float*>(smem + SM_C2);
    float* s_pbv = reinterpret_cast<float*>(smem + SM_PBV);
    float* s_psv = reinterpret_cast<float*>(smem + SM_PSV);
    int*   s_pbi = reinterpret_cast<int*>(smem + SM_PBI);

    for (int i = tid; i < KCB; i += NTH) s_c2[i] = g_c2[i];

    // per-thread ldmatrix offsets (within buffer)
    uint32_t aoff[2], boff[8];
    #pragma unroll
    for (int mt = 0; mt < 2; ++mt) {
        int row = mwarp * 32 + mt * 16 + (lane & 7) + ((lane >> 3) & 1) * 8;
        aoff[mt] = row * STRIDE_B + (lane >> 4) * 16;
    }
    #pragma unroll
    for (int p = 0; p < 8; ++p) {
        int n = nwarp * 128 + p * 16 + (lane & 7) + (lane >> 4) * 8;
        boff[p] = A_BYTES + n * STRIDE_B + ((lane >> 3) & 1) * 16;
    }

    float acc[2][16][4];
    float bv[4], sv[4]; int bi[4];
    #pragma unroll
    for (int r = 0; r < 4; ++r) { bv[r] = FLT_MAX; sv[r] = FLT_MAX; bi[r] = 0; }

    stage_load(0, rowbase, sbase, tid);

    for (int s = 0; s < NSTG; ++s) {
        if (s + 1 < NSTG) { stage_load(s + 1, rowbase, sbase, tid); CPWAIT1(); }
        else              { CPWAIT0(); }
        __syncthreads();

        if ((s % STG_PER_PH) == 0) {
            #pragma unroll
            for (int mt = 0; mt < 2; ++mt)
                #pragma unroll
                for (int nt = 0; nt < 16; ++nt)
                    #pragma unroll
                    for (int r = 0; r < 4; ++r) acc[mt][nt][r] = 0.f;
        }

        const uint32_t bufo = sbase + SM_BUF + (uint32_t)(s & 1) * BUF_BYTES;
        #pragma unroll
        for (int ks = 0; ks < 4; ++ks) {
            uint32_t a0[4], a1[4];
            LDSM4(a0[0], a0[1], a0[2], a0[3], bufo + aoff[0] + ks * 32);
            LDSM4(a1[0], a1[1], a1[2], a1[3], bufo + aoff[1] + ks * 32);
            #pragma unroll
            for (int p = 0; p < 8; ++p) {
                uint32_t b0, b1, b2, b3;
                LDSM4(b0, b1, b2, b3, bufo + boff[p] + ks * 32);
                mma_bf16(acc[0][2 * p],     a0, b0, b1);
                mma_bf16(acc[0][2 * p + 1], a0, b2, b3);
                mma_bf16(acc[1][2 * p],     a1, b0, b1);
                mma_bf16(acc[1][2 * p + 1], a1, b2, b3);
            }
        }

        if ((s % STG_PER_PH) == STG_PER_PH - 1) {
            const int ph = s / STG_PER_PH;
            const int cbase = ph * BN + nwarp * 128 + (lane & 3) * 2;
            #pragma unroll
            for (int nt = 0; nt < 16; ++nt) {
                const int col0 = cbase + nt * 8;
                const float c2a = s_c2[col0], c2b = s_c2[col0 + 1];
                #pragma unroll
                for (int mt = 0; mt < 2; ++mt) {
                    const float* a = acc[mt][nt];
                    const int r0 = mt * 2, r1 = mt * 2 + 1;
                    float s0 = fmaf(-2.f, a[0], c2a);
                    float s1 = fmaf(-2.f, a[1], c2b);
                    float s2 = fmaf(-2.f, a[2], c2a);
                    float s3 = fmaf(-2.f, a[3], c2b);
                    if (s0 < bv[r0]) { sv[r0] = bv[r0]; bv[r0] = s0; bi[r0] = col0; }
                    else if (s0 < sv[r0]) sv[r0] = s0;
                    if (s1 < bv[r0]) { sv[r0] = bv[r0]; bv[r0] = s1; bi[r0] = col0 + 1; }
                    else if (s1 < sv[r0]) sv[r0] = s1;
                    if (s2 < bv[r1]) { sv[r1] = bv[r1]; bv[r1] = s2; bi[r1] = col0; }
                    else if (s2 < sv[r1]) sv[r1] = s2;
                    if (s3 < bv[r1]) { sv[r1] = bv[r1]; bv[r1] = s3; bi[r1] = col0 + 1; }
                    else if (s3 < sv[r1]) sv[r1] = s3;
                }
            }
        }
        __syncthreads();   // guard buffer reuse before next prefetch overwrites
    }

    // quad reduction (lanes sharing rows: same lane/4)
    #pragma unroll
    for (int r = 0; r < 4; ++r) {
        #pragma unroll
        for (int off = 1; off <= 2; off <<= 1) {
            float ov = __shfl_xor_sync(0xffffffffu, bv[r], off);
            float os = __shfl_xor_sync(0xffffffffu, sv[r], off);
            int   oi = __shfl_xor_sync(0xffffffffu, bi[r], off);
            if (ov < bv[r] || (ov == bv[r] && oi < bi[r])) {
                sv[r] = fminf(bv[r], os); bv[r] = ov; bi[r] = oi;
            } else {
                sv[r] = fminf(sv[r], ov);
            }
        }
    }
    if ((lane & 3) == 0) {
        #pragma unroll
        for (int r = 0; r < 4; ++r) {
            int rowloc = mwarp * 32 + (lane >> 2) + r * 8;
            s_pbv[nwarp * 128 + rowloc] = bv[r];
            s_psv[nwarp * 128 + rowloc] = sv[r];
            s_pbi[nwarp * 128 + rowloc] = bi[r];
        }
    }
    __syncthreads();
    if (tid < BM) {
        float b0 = s_pbv[tid],       s0 = s_psv[tid];
        float b1 = s_pbv[128 + tid], s1 = s_psv[128 + tid];
        int   i0 = s_pbi[tid],       i1 = s_pbi[128 + tid];
        float fb, fs; int fi;
        if (b0 < b1 || (b0 == b1 && i0 < i1)) { fb = b0; fi = i0; fs = fminf(s0, b1); }
        else                                  { fb = b1; fi = i1; fs = fminf(s1, b0); }
        int row = rowbase + tid;
        g_best[row] = fi;
        if (fs - fb < TAU) {
            int slot = atomicAdd(&g_flag_count, 1);
            if (slot < CAP) g_flag_rows[slot] = row;
        }
    }
}

// ================= pass 2: fp64 rescue (proven) =================
__global__ __launch_bounds__(256) void rescue_kernel(
    const float* __restrict__ x,
    const float* __restrict__ cb)
{
    __shared__ float sx[D];
    __shared__ float wv[8];
    __shared__ int   wi[8];

    const int tid  = threadIdx.x;
    const int wid  = tid >> 5;
    const int lane = tid & 31;
    int total = g_flag_count;
    if (total > CAP) total = CAP;

    for (int f = blockIdx.x; f < total; f += gridDim.x) {
        const int row = g_flag_rows[f];
        for (int i = tid; i < D; i += 256) sx[i] = x[(size_t)row * D + i];
        __syncthreads();

        double x2 = 0.0;
        for (int e = lane; e < D; e += 32) { double v = (double)sx[e]; x2 += v * v; }
        #pragma unroll
        for (int o = 16; o; o >>= 1) x2 += __shfl_xor_sync(0xffffffffu, x2, o);
        const float x2f = (float)x2;

        float bv = FLT_MAX;
        int   bi = 1 << 30;
        for (int cw = wid; cw < KCB; cw += 8) {
            const float* c = cb + (size_t)cw * D;
            double dot = 0.0;
            for (int e = lane; e < D; e += 32)
                dot += (double)sx[e] * (double)c[e];
            #pragma unroll
            for (int o = 16; o; o >>= 1) dot += __shfl_xor_sync(0xffffffffu, dot, o);
            float d2 = (x2f - 2.0f * (float)dot) + g_c2[cw];
            if (d2 < bv) { bv = d2; bi = cw; }
        }
        if (lane == 0) { wv[wid] = bv; wi[wid] = bi; }
        __syncthreads();
        if (tid == 0) {
            float fbv = wv[0]; int fbi = wi[0];
            #pragma unroll
            for (int t = 1; t < 8; ++t)
                if (wv[t] < fbv || (wv[t] == fbv && wi[t] < fbi)) { fbv = wv[t]; fbi = wi[t]; }
            g_best[row] = fbi;
        }
        __syncthreads();
    }
}

// ================= pass 3: gather =================
__global__ __launch_bounds__(256) void gather_kernel(
    const float* __restrict__ cb,
    float* __restrict__ out)
{
    const int row = blockIdx.x * 2 + (threadIdx.x >> 7);
    const int c4  = threadIdx.x & 127;
    const int bi  = g_best[row];
    reinterpret_cast<float4*>(out + (size_t)row * D)[c4] =
        reinterpret_cast<const float4*>(cb + (size_t)bi * D)[c4];
}

extern "C" void kernel_launch(void* const* d_in, const int* in_sizes, int n_in,
                              void* d_out, int out_size) {
    const float* x  = (const float*)d_in[0];   // [65536, 512]
    const float* cb = (const float*)d_in[1];   // [1024, 512]
    float* out = (float*)d_out;
    int nrows = in_sizes[0] / D;               // 65536

    cudaFuncSetAttribute(vq_mma_kernel,
                         cudaFuncAttributeMaxDynamicSharedMemorySize, SM_TOTAL);

    prep_x<<<(int)((size_t)nrows * D / 4 / 512), 512>>>(x);
    prep_cb<<<KCB * D / 4 / 512, 512>>>(cb);
    c2_kernel<<<KCB / 8, 256>>>(cb);
    vq_mma_kernel<<<nrows / BM, NTH, SM_TOTAL>>>();
    rescue_kernel<<<296, 256>>>(x, cb);
    gather_kernel<<<nrows / 2, 256>>>(cb, out);
}

// round 6
// speedup vs baseline: 3.2200x; 1.0245x over previous
#include <cuda_runtime.h>
#include <cuda_bf16.h>
#include <cfloat>
#include <cstdint>

#define D        512
#define KCB      1024
#define NROWS    65536
#define TAU      0.01f
#define CAP      65536

#define BM       128            // rows per CTA
#define BN       256            // codewords per phase
#define NPH      4              // 1024 / 256
#define KC       128            // K elems per stage
#define NTERM    3              // hi*hi, hi*lo, lo*hi
#define STG_PER_PH (NTERM * (D / KC))   // 12
#define NSTG     (NPH * STG_PER_PH)     // 48
#define NTH      256

// smem layout (bytes)
#define SM_C2    0               // float[1024]
#define SM_PBV   4096            // float[256]
#define SM_PSV   5120            // float[256]
#define SM_PBI   6144            // int[256]
#define SM_BUF   8192
#define STRIDE_B 272             // 256B data + 16B pad: rows offset 4 banks -> conflict-free
#define A_BYTES  (BM * STRIDE_B)          // 34816
#define B_BYTES  (BN * STRIDE_B)          // 69632
#define BUF_BYTES (A_BYTES + B_BYTES)     // 104448
#define SM_TOTAL (SM_BUF + 2 * BUF_BYTES) // 217088

// ---- device scratch (no cudaMalloc allowed) ----
__device__ __nv_bfloat16 g_xhi[(size_t)NROWS * D];   // 64 MB
__device__ __nv_bfloat16 g_xlo[(size_t)NROWS * D];   // 64 MB
__device__ __nv_bfloat16 g_cbhi[KCB * D];            // 1 MB
__device__ __nv_bfloat16 g_cblo[KCB * D];            // 1 MB
__device__ float g_c2[KCB];
__device__ int   g_best[NROWS];
__device__ int   g_flag_rows[CAP];
__device__ int   g_flag_count;

// ================= PTX helpers (baseline sm_80 features only) =================
__device__ __forceinline__ uint32_t smem_u32(const void* p) {
    uint32_t a;
    asm("{ .reg .u64 t; cvta.to.shared.u64 t, %1; cvt.u32.u64 %0, t; }" : "=r"(a) : "l"(p));
    return a;
}
#define CP16(s, g)   asm volatile("cp.async.ca.shared.global [%0], [%1], 16;" :: "r"(s), "l"(g))
#define CPCOMMIT()   asm volatile("cp.async.commit_group;")
#define CPWAIT0()    asm volatile("cp.async.wait_group 0;")
#define LDSM4(r0, r1, r2, r3, a) \
    asm volatile("ldmatrix.sync.aligned.m8n8.x4.shared.b16 {%0,%1,%2,%3}, [%4];" \
                 : "=r"(r0), "=r"(r1), "=r"(r2), "=r"(r3) : "r"(a))

__device__ __forceinline__ void mma_bf16(float* c, const uint32_t* a, uint32_t b0, uint32_t b1) {
    asm volatile(
        "mma.sync.aligned.m16n8k16.row.col.f32.bf16.bf16.f32 "
        "{%0,%1,%2,%3}, {%4,%5,%6,%7}, {%8,%9}, {%0,%1,%2,%3};"
        : "+f"(c[0]), "+f"(c[1]), "+f"(c[2]), "+f"(c[3])
        : "r"(a[0]), "r"(a[1]), "r"(a[2]), "r"(a[3]), "r"(b0), "r"(b1));
}

// ================= prep: split f32 -> bf16 hi/lo =================
__global__ __launch_bounds__(512) void prep_x(const float* __restrict__ x) {
    size_t i = (size_t)blockIdx.x * 512 + threadIdx.x;     // over float4s
    float4 v = reinterpret_cast<const float4*>(x)[i];
    __nv_bfloat162 h01 = __floats2bfloat162_rn(v.x, v.y);
    __nv_bfloat162 h23 = __floats2bfloat162_rn(v.z, v.w);
    __nv_bfloat162 l01 = __floats2bfloat162_rn(v.x - __bfloat162float(h01.x),
                                               v.y - __bfloat162float(h01.y));
    __nv_bfloat162 l23 = __floats2bfloat162_rn(v.z - __bfloat162float(h23.x),
                                               v.w - __bfloat162float(h23.y));
    uint2 hw, lw;
    hw.x = *reinterpret_cast<uint32_t*>(&h01); hw.y = *reinterpret_cast<uint32_t*>(&h23);
    lw.x = *reinterpret_cast<uint32_t*>(&l01); lw.y = *reinterpret_cast<uint32_t*>(&l23);
    reinterpret_cast<uint2*>(g_xhi)[i] = hw;
    reinterpret_cast<uint2*>(g_xlo)[i] = lw;
}
__global__ __launch_bounds__(512) void prep_cb(const float* __restrict__ cb) {
    size_t i = (size_t)blockIdx.x * 512 + threadIdx.x;
    float4 v = reinterpret_cast<const float4*>(cb)[i];
    __nv_bfloat162 h01 = __floats2bfloat162_rn(v.x, v.y);
    __nv_bfloat162 h23 = __floats2bfloat162_rn(v.z, v.w);
    __nv_bfloat162 l01 = __floats2bfloat162_rn(v.x - __bfloat162float(h01.x),
                                               v.y - __bfloat162float(h01.y));
    __nv_bfloat162 l23 = __floats2bfloat162_rn(v.z - __bfloat162float(h23.x),
                                               v.w - __bfloat162float(h23.y));
    uint2 hw, lw;
    hw.x = *reinterpret_cast<uint32_t*>(&h01); hw.y = *reinterpret_cast<uint32_t*>(&h23);
    lw.x = *reinterpret_cast<uint32_t*>(&l01); lw.y = *reinterpret_cast<uint32_t*>(&l23);
    reinterpret_cast<uint2*>(g_cbhi)[i] = hw;
    reinterpret_cast<uint2*>(g_cblo)[i] = lw;
}

// ================= pass 0: ||c||^2 (fp64 accum) + reset flags =================
__global__ void c2_kernel(const float* __restrict__ cb) {
    if (blockIdx.x == 0 && threadIdx.x == 0) g_flag_count = 0;
    int cw   = blockIdx.x * (blockDim.x >> 5) + (threadIdx.x >> 5);
    int lane = threadIdx.x & 31;
    const float4* p = reinterpret_cast<const float4*>(cb + (size_t)cw * D);
    double s = 0.0;
    for (int t = lane; t < D / 4; t += 32) {
        float4 v = p[t];
        s += (double)v.x * v.x + (double)v.y * v.y + (double)v.z * v.z + (double)v.w * v.w;
    }
    #pragma unroll
    for (int o = 16; o; o >>= 1) s += __shfl_xor_sync(0xffffffffu, s, o);
    if (lane == 0) g_c2[cw] = (float)s;
}

// ================= pass 1: bf16-split HMMA screen =================
__device__ __forceinline__ void stage_load(int s, int rowbase, uint32_t sbase, int tid) {
    const int ph = s / STG_PER_PH;
    const int r  = s % STG_PER_PH;
    const int t  = r >> 2;            // 0,1,2 -> hi*hi, hi*lo, lo*hi
    const int k0 = (r & 3) * KC;
    const __nv_bfloat16* asrc = (t == 2) ? g_xlo : g_xhi;
    const __nv_bfloat16* bsrc = (t == 1) ? g_cblo : g_cbhi;
    const uint32_t bufo = sbase + SM_BUF + (uint32_t)(s & 1) * BUF_BYTES;
    #pragma unroll
    for (int i = 0; i < 8; ++i) {                 // A: 128 rows x 16 chunks
        int id = tid + i * NTH;
        int row = id >> 4, kc = id & 15;
        CP16(bufo + row * STRIDE_B + kc * 16,
             asrc + (size_t)(rowbase + row) * D + k0 + kc * 8);
    }
    #pragma unroll
    for (int i = 0; i < 16; ++i) {                // B: 256 rows x 16 chunks
        int id = tid + i * NTH;
        int n = id >> 4, kc = id & 15;
        CP16(bufo + A_BYTES + n * STRIDE_B + kc * 16,
             bsrc + (size_t)(ph * BN + n) * D + k0 + kc * 8);
    }
    CPCOMMIT();
}

__global__ __launch_bounds__(NTH, 1) void vq_mma_kernel() {
    extern __shared__ char smem[];
    const uint32_t sbase = smem_u32(smem);
    const int tid   = threadIdx.x;
    const int lane  = tid & 31;
    const int wid   = tid >> 5;
    const int mwarp = wid >> 1;       // 0..3 -> 32 rows each
    const int nwarp = wid & 1;        // 0..1 -> 128 cols each
    const int rowbase = blockIdx.x * BM;

    float* s_c2  = reinterpret_cast<float*>(smem + SM_C2);
    float* s_pbv = reinterpret_cast<float*>(smem + SM_PBV);
    float* s_psv = reinterpret_cast<float*>(smem + SM_PSV);
    int*   s_pbi = reinterpret_cast<int*>(smem + SM_PBI);

    for (int i = tid; i < KCB; i += NTH) s_c2[i] = g_c2[i];

    // per-thread ldmatrix offsets (within buffer)
    uint32_t aoff[2], boff[8];
    #pragma unroll
    for (int mt = 0; mt < 2; ++mt) {
        int row = mwarp * 32 + mt * 16 + (lane & 7) + ((lane >> 3) & 1) * 8;
        aoff[mt] = row * STRIDE_B + (lane >> 4) * 16;
    }
    #pragma unroll
    for (int p = 0; p < 8; ++p) {
        int n = nwarp * 128 + p * 16 + (lane & 7) + (lane >> 4) * 8;
        boff[p] = A_BYTES + n * STRIDE_B + ((lane >> 3) & 1) * 16;
    }

    float acc[2][16][4];
    float bv[4], sv[4]; int bi[4];
    #pragma unroll
    for (int r = 0; r < 4; ++r) { bv[r] = FLT_MAX; sv[r] = FLT_MAX; bi[r] = 0; }

    stage_load(0, rowbase, sbase, tid);

    for (int s = 0; s < NSTG; ++s) {
        CPWAIT0();            // buf[s&1] fully staged
        __syncthreads();      // all warps done with compute(s-1) -> buf[(s+1)&1] reusable
        if (s + 1 < NSTG) stage_load(s + 1, rowbase, sbase, tid);   // overlaps compute(s)

        if ((s % STG_PER_PH) == 0) {
            #pragma unroll
            for (int mt = 0; mt < 2; ++mt)
                #pragma unroll
                for (int nt = 0; nt < 16; ++nt)
                    #pragma unroll
                    for (int r = 0; r < 4; ++r) acc[mt][nt][r] = 0.f;
        }

        const uint32_t bufo = sbase + SM_BUF + (uint32_t)(s & 1) * BUF_BYTES;
        #pragma unroll
        for (int ks = 0; ks < 8; ++ks) {
            uint32_t a0[4], a1[4];
            LDSM4(a0[0], a0[1], a0[2], a0[3], bufo + aoff[0] + ks * 32);
            LDSM4(a1[0], a1[1], a1[2], a1[3], bufo + aoff[1] + ks * 32);
            #pragma unroll
            for (int p = 0; p < 8; ++p) {
                uint32_t b0, b1, b2, b3;
                LDSM4(b0, b1, b2, b3, bufo + boff[p] + ks * 32);
                mma_bf16(acc[0][2 * p],     a0, b0, b1);
                mma_bf16(acc[0][2 * p + 1], a0, b2, b3);
                mma_bf16(acc[1][2 * p],     a1, b0, b1);
                mma_bf16(acc[1][2 * p + 1], a1, b2, b3);
            }
        }

        if ((s % STG_PER_PH) == STG_PER_PH - 1) {
            const int ph = s / STG_PER_PH;
            const int cbase = ph * BN + nwarp * 128 + (lane & 3) * 2;
            #pragma unroll
            for (int nt = 0; nt < 16; ++nt) {
                const int col0 = cbase + nt * 8;
                const float c2a = s_c2[col0], c2b = s_c2[col0 + 1];
                #pragma unroll
                for (int mt = 0; mt < 2; ++mt) {
                    const float* a = acc[mt][nt];
                    const int r0 = mt * 2, r1 = mt * 2 + 1;
                    float s0 = fmaf(-2.f, a[0], c2a);
                    float s1 = fmaf(-2.f, a[1], c2b);
                    float s2 = fmaf(-2.f, a[2], c2a);
                    float s3 = fmaf(-2.f, a[3], c2b);
                    if (s0 < bv[r0]) { sv[r0] = bv[r0]; bv[r0] = s0; bi[r0] = col0; }
                    else if (s0 < sv[r0]) sv[r0] = s0;
                    if (s1 < bv[r0]) { sv[r0] = bv[r0]; bv[r0] = s1; bi[r0] = col0 + 1; }
                    else if (s1 < sv[r0]) sv[r0] = s1;
                    if (s2 < bv[r1]) { sv[r1] = bv[r1]; bv[r1] = s2; bi[r1] = col0; }
                    else if (s2 < sv[r1]) sv[r1] = s2;
                    if (s3 < bv[r1]) { sv[r1] = bv[r1]; bv[r1] = s3; bi[r1] = col0 + 1; }
                    else if (s3 < sv[r1]) sv[r1] = s3;
                }
            }
        }
    }

    // quad reduction (lanes sharing rows)
    #pragma unroll
    for (int r = 0; r < 4; ++r) {
        #pragma unroll
        for (int off = 1; off <= 2; off <<= 1) {
            float ov = __shfl_xor_sync(0xffffffffu, bv[r], off);
            float os = __shfl_xor_sync(0xffffffffu, sv[r], off);
            int   oi = __shfl_xor_sync(0xffffffffu, bi[r], off);
            if (ov < bv[r] || (ov == bv[r] && oi < bi[r])) {
                sv[r] = fminf(bv[r], os); bv[r] = ov; bi[r] = oi;
            } else {
                sv[r] = fminf(sv[r], ov);
            }
        }
    }
    __syncthreads();   // acc reads done; reuse smem front for reduction
    if ((lane & 3) == 0) {
        #pragma unroll
        for (int r = 0; r < 4; ++r) {
            int rowloc = mwarp * 32 + (lane >> 2) + r * 8;
            s_pbv[nwarp * 128 + rowloc] = bv[r];
            s_psv[nwarp * 128 + rowloc] = sv[r];
            s_pbi[nwarp * 128 + rowloc] = bi[r];
        }
    }
    __syncthreads();
    if (tid < BM) {
        float b0 = s_pbv[tid],       s0 = s_psv[tid];
        float b1 = s_pbv[128 + tid], s1 = s_psv[128 + tid];
        int   i0 = s_pbi[tid],       i1 = s_pbi[128 + tid];
        float fb, fs; int fi;
        if (b0 < b1 || (b0 == b1 && i0 < i1)) { fb = b0; fi = i0; fs = fminf(s0, b1); }
        else                                  { fb = b1; fi = i1; fs = fminf(s1, b0); }
        int row = rowbase + tid;
        g_best[row] = fi;
        if (fs - fb < TAU) {
            int slot = atomicAdd(&g_flag_count, 1);
            if (slot < CAP) g_flag_rows[slot] = row;
        }
    }
}

// ================= pass 2: fp64 rescue (proven) =================
__global__ __launch_bounds__(256) void rescue_kernel(
    const float* __restrict__ x,
    const float* __restrict__ cb)
{
    __shared__ float sx[D];
    __shared__ float wv[8];
    __shared__ int   wi[8];

    const int tid  = threadIdx.x;
    const int wid  = tid >> 5;
    const int lane = tid & 31;
    int total = g_flag_count;
    if (total > CAP) total = CAP;

    for (int f = blockIdx.x; f < total; f += gridDim.x) {
        const int row = g_flag_rows[f];
        for (int i = tid; i < D; i += 256) sx[i] = x[(size_t)row * D + i];
        __syncthreads();

        double x2 = 0.0;
        for (int e = lane; e < D; e += 32) { double v = (double)sx[e]; x2 += v * v; }
        #pragma unroll
        for (int o = 16; o; o >>= 1) x2 += __shfl_xor_sync(0xffffffffu, x2, o);
        const float x2f = (float)x2;

        float bv = FLT_MAX;
        int   bi = 1 << 30;
        for (int cw = wid; cw < KCB; cw += 8) {
            const float* c = cb + (size_t)cw * D;
            double dot = 0.0;
            for (int e = lane; e < D; e += 32)
                dot += (double)sx[e] * (double)c[e];
            #pragma unroll
            for (int o = 16; o; o >>= 1) dot += __shfl_xor_sync(0xffffffffu, dot, o);
            float d2 = (x2f - 2.0f * (float)dot) + g_c2[cw];
            if (d2 < bv) { bv = d2; bi = cw; }
        }
        if (lane == 0) { wv[wid] = bv; wi[wid] = bi; }
        __syncthreads();
        if (tid == 0) {
            float fbv = wv[0]; int fbi = wi[0];
            #pragma unroll
            for (int t = 1; t < 8; ++t)
                if (wv[t] < fbv || (wv[t] == fbv && wi[t] < fbi)) { fbv = wv[t]; fbi = wi[t]; }
            g_best[row] = fbi;
        }
        __syncthreads();
    }
}

// ================= pass 3: gather (warp per row) =================
__global__ __launch_bounds__(256) void gather_kernel(
    const float* __restrict__ cb,
    float* __restrict__ out)
{
    const int row  = blockIdx.x * 8 + (threadIdx.x >> 5);
    const int lane = threadIdx.x & 31;
    const int bi   = g_best[row];
    const float4* src = reinterpret_cast<const float4*>(cb + (size_t)bi * D);
    float4* dst = reinterpret_cast<float4*>(out + (size_t)row * D);
    #pragma unroll
    for (int i = 0; i < 4; ++i)
        dst[lane + i * 32] = src[lane + i * 32];
}

extern "C" void kernel_launch(void* const* d_in, const int* in_sizes, int n_in,
                              void* d_out, int out_size) {
    const float* x  = (const float*)d_in[0];   // [65536, 512]
    const float* cb = (const float*)d_in[1];   // [1024, 512]
    float* out = (float*)d_out;
    int nrows = in_sizes[0] / D;               // 65536

    cudaFuncSetAttribute(vq_mma_kernel,
                         cudaFuncAttributeMaxDynamicSharedMemorySize, SM_TOTAL);

    prep_x<<<(int)((size_t)nrows * D / 4 / 512), 512>>>(x);
    prep_cb<<<KCB * D / 4 / 512, 512>>>(cb);
    c2_kernel<<<KCB / 8, 256>>>(cb);
    vq_mma_kernel<<<nrows / BM, NTH, SM_TOTAL>>>();
    rescue_kernel<<<296, 256>>>(x, cb);
    gather_kernel<<<nrows / 8, 256>>>(cb, out);
}

// round 7
// speedup vs baseline: 3.2819x; 1.0192x over previous
#include <cuda_runtime.h>
#include <cuda_bf16.h>
#include <cfloat>
#include <cstdint>

#define D        512
#define KCB      1024
#define NROWS    65536
#define TAU      0.01f
#define CAP      65536

#define BM       128            // rows per CTA
#define BN       256            // codewords per phase
#define NPH      4              // 1024 / 256
#define KC       128            // K elems per stage
#define NTERM    3              // hi*hi, hi*lo, lo*hi
#define STG_PER_PH (NTERM * (D / KC))   // 12
#define NSTG     (NPH * STG_PER_PH)     // 48
#define NTH      512

// smem layout (bytes)
#define SM_C2    0               // float[1024]
#define SM_PBV   4096            // float[512]
#define SM_PSV   6144            // float[512]
#define SM_PBI   8192            // int[512]
#define SM_BUF   10240
#define STRIDE_B 272             // 256B data + 16B pad -> conflict-free ldmatrix
#define A_BYTES  (BM * STRIDE_B)          // 34816
#define B_BYTES  (BN * STRIDE_B)          // 69632
#define BUF_BYTES (A_BYTES + B_BYTES)     // 104448
#define SM_TOTAL (SM_BUF + 2 * BUF_BYTES) // 219136

// ---- device scratch (no cudaMalloc allowed) ----
__device__ __nv_bfloat16 g_xhi[(size_t)NROWS * D];   // 64 MB
__device__ __nv_bfloat16 g_xlo[(size_t)NROWS * D];   // 64 MB
__device__ __nv_bfloat16 g_cbhi[KCB * D];            // 1 MB
__device__ __nv_bfloat16 g_cblo[KCB * D];            // 1 MB
__device__ float g_c2[KCB];
__device__ int   g_best[NROWS];
__device__ int   g_flag_rows[CAP];
__device__ int   g_flag_count;

// ================= PTX helpers (baseline sm_80 features only) =================
__device__ __forceinline__ uint32_t smem_u32(const void* p) {
    uint32_t a;
    asm("{ .reg .u64 t; cvta.to.shared.u64 t, %1; cvt.u32.u64 %0, t; }" : "=r"(a) : "l"(p));
    return a;
}
#define CP16(s, g)   asm volatile("cp.async.ca.shared.global [%0], [%1], 16;" :: "r"(s), "l"(g))
#define CPCOMMIT()   asm volatile("cp.async.commit_group;")
#define CPWAIT0()    asm volatile("cp.async.wait_group 0;")
#define LDSM4(r0, r1, r2, r3, a) \
    asm volatile("ldmatrix.sync.aligned.m8n8.x4.shared.b16 {%0,%1,%2,%3}, [%4];" \
                 : "=r"(r0), "=r"(r1), "=r"(r2), "=r"(r3) : "r"(a))

__device__ __forceinline__ void mma_bf16(float* c, const uint32_t* a, uint32_t b0, uint32_t b1) {
    asm volatile(
        "mma.sync.aligned.m16n8k16.row.col.f32.bf16.bf16.f32 "
        "{%0,%1,%2,%3}, {%4,%5,%6,%7}, {%8,%9}, {%0,%1,%2,%3};"
        : "+f"(c[0]), "+f"(c[1]), "+f"(c[2]), "+f"(c[3])
        : "r"(a[0]), "r"(a[1]), "r"(a[2]), "r"(a[3]), "r"(b0), "r"(b1));
}

// ================= prep: split f32 -> bf16 hi/lo =================
__global__ __launch_bounds__(512) void prep_x(const float* __restrict__ x) {
    size_t i = (size_t)blockIdx.x * 512 + threadIdx.x;     // over float4s
    float4 v = reinterpret_cast<const float4*>(x)[i];
    __nv_bfloat162 h01 = __floats2bfloat162_rn(v.x, v.y);
    __nv_bfloat162 h23 = __floats2bfloat162_rn(v.z, v.w);
    __nv_bfloat162 l01 = __floats2bfloat162_rn(v.x - __bfloat162float(h01.x),
                                               v.y - __bfloat162float(h01.y));
    __nv_bfloat162 l23 = __floats2bfloat162_rn(v.z - __bfloat162float(h23.x),
                                               v.w - __bfloat162float(h23.y));
    uint2 hw, lw;
    hw.x = *reinterpret_cast<uint32_t*>(&h01); hw.y = *reinterpret_cast<uint32_t*>(&h23);
    lw.x = *reinterpret_cast<uint32_t*>(&l01); lw.y = *reinterpret_cast<uint32_t*>(&l23);
    reinterpret_cast<uint2*>(g_xhi)[i] = hw;
    reinterpret_cast<uint2*>(g_xlo)[i] = lw;
}
__global__ __launch_bounds__(512) void prep_cb(const float* __restrict__ cb) {
    size_t i = (size_t)blockIdx.x * 512 + threadIdx.x;
    float4 v = reinterpret_cast<const float4*>(cb)[i];
    __nv_bfloat162 h01 = __floats2bfloat162_rn(v.x, v.y);
    __nv_bfloat162 h23 = __floats2bfloat162_rn(v.z, v.w);
    __nv_bfloat162 l01 = __floats2bfloat162_rn(v.x - __bfloat162float(h01.x),
                                               v.y - __bfloat162float(h01.y));
    __nv_bfloat162 l23 = __floats2bfloat162_rn(v.z - __bfloat162float(h23.x),
                                               v.w - __bfloat162float(h23.y));
    uint2 hw, lw;
    hw.x = *reinterpret_cast<uint32_t*>(&h01); hw.y = *reinterpret_cast<uint32_t*>(&h23);
    lw.x = *reinterpret_cast<uint32_t*>(&l01); lw.y = *reinterpret_cast<uint32_t*>(&l23);
    reinterpret_cast<uint2*>(g_cbhi)[i] = hw;
    reinterpret_cast<uint2*>(g_cblo)[i] = lw;
}

// ================= pass 0: ||c||^2 (fp64 accum) + reset flags =================
__global__ void c2_kernel(const float* __restrict__ cb) {
    if (blockIdx.x == 0 && threadIdx.x == 0) g_flag_count = 0;
    int cw   = blockIdx.x * (blockDim.x >> 5) + (threadIdx.x >> 5);
    int lane = threadIdx.x & 31;
    const float4* p = reinterpret_cast<const float4*>(cb + (size_t)cw * D);
    double s = 0.0;
    for (int t = lane; t < D / 4; t += 32) {
        float4 v = p[t];
        s += (double)v.x * v.x + (double)v.y * v.y + (double)v.z * v.z + (double)v.w * v.w;
    }
    #pragma unroll
    for (int o = 16; o; o >>= 1) s += __shfl_xor_sync(0xffffffffu, s, o);
    if (lane == 0) g_c2[cw] = (float)s;
}

// ================= pass 1: bf16-split HMMA screen (16 warps) =================
__device__ __forceinline__ void stage_load(int s, int rowbase, uint32_t sbase, int tid) {
    const int ph = s / STG_PER_PH;
    const int r  = s % STG_PER_PH;
    const int t  = r >> 2;            // 0,1,2 -> hi*hi, hi*lo, lo*hi
    const int k0 = (r & 3) * KC;
    const __nv_bfloat16* asrc = (t == 2) ? g_xlo : g_xhi;
    const __nv_bfloat16* bsrc = (t == 1) ? g_cblo : g_cbhi;
    const uint32_t bufo = sbase + SM_BUF + (uint32_t)(s & 1) * BUF_BYTES;
    #pragma unroll
    for (int i = 0; i < 4; ++i) {                 // A: 128 rows x 16 chunks
        int id = tid + i * NTH;
        int row = id >> 4, kc = id & 15;
        CP16(bufo + row * STRIDE_B + kc * 16,
             asrc + (size_t)(rowbase + row) * D + k0 + kc * 8);
    }
    #pragma unroll
    for (int i = 0; i < 8; ++i) {                 // B: 256 rows x 16 chunks
        int id = tid + i * NTH;
        int n = id >> 4, kc = id & 15;
        CP16(bufo + A_BYTES + n * STRIDE_B + kc * 16,
             bsrc + (size_t)(ph * BN + n) * D + k0 + kc * 8);
    }
    CPCOMMIT();
}

__global__ __launch_bounds__(NTH, 1) void vq_mma_kernel() {
    extern __shared__ char smem[];
    const uint32_t sbase = smem_u32(smem);
    const int tid   = threadIdx.x;
    const int lane  = tid & 31;
    const int wid   = tid >> 5;
    const int mwarp = wid >> 2;       // 0..3 -> 32 rows each
    const int nwarp = wid & 3;        // 0..3 -> 64 cols each
    const int rowbase = blockIdx.x * BM;

    float* s_c2  = reinterpret_cast<float*>(smem + SM_C2);
    float* s_pbv = reinterpret_cast<float*>(smem + SM_PBV);
    float* s_psv = reinterpret_cast<float*>(smem + SM_PSV);
    int*   s_pbi = reinterpret_cast<int*>(smem + SM_PBI);

    for (int i = tid; i < KCB; i += NTH) s_c2[i] = g_c2[i];

    // per-thread ldmatrix offsets (within buffer)
    uint32_t aoff[2], boff[4];
    #pragma unroll
    for (int mt = 0; mt < 2; ++mt) {
        int row = mwarp * 32 + mt * 16 + (lane & 7) + ((lane >> 3) & 1) * 8;
        aoff[mt] = row * STRIDE_B + (lane >> 4) * 16;
    }
    #pragma unroll
    for (int p = 0; p < 4; ++p) {
        int n = nwarp * 64 + p * 16 + (lane & 7) + (lane >> 4) * 8;
        boff[p] = A_BYTES + n * STRIDE_B + ((lane >> 3) & 1) * 16;
    }

    float acc[2][8][4];
    float bv[4], sv[4]; int bi[4];
    #pragma unroll
    for (int r = 0; r < 4; ++r) { bv[r] = FLT_MAX; sv[r] = FLT_MAX; bi[r] = 0; }

    stage_load(0, rowbase, sbase, tid);

    for (int s = 0; s < NSTG; ++s) {
        CPWAIT0();            // buf[s&1] fully staged
        __syncthreads();      // all warps done with compute(s-1) -> buf[(s+1)&1] reusable
        if (s + 1 < NSTG) stage_load(s + 1, rowbase, sbase, tid);   // overlaps compute(s)

        if ((s % STG_PER_PH) == 0) {
            #pragma unroll
            for (int mt = 0; mt < 2; ++mt)
                #pragma unroll
                for (int nt = 0; nt < 8; ++nt)
                    #pragma unroll
                    for (int r = 0; r < 4; ++r) acc[mt][nt][r] = 0.f;
        }

        const uint32_t bufo = sbase + SM_BUF + (uint32_t)(s & 1) * BUF_BYTES;
        #pragma unroll
        for (int ks = 0; ks < 8; ++ks) {
            uint32_t a0[4], a1[4];
            LDSM4(a0[0], a0[1], a0[2], a0[3], bufo + aoff[0] + ks * 32);
            LDSM4(a1[0], a1[1], a1[2], a1[3], bufo + aoff[1] + ks * 32);
            #pragma unroll
            for (int p = 0; p < 4; ++p) {
                uint32_t b0, b1, b2, b3;
                LDSM4(b0, b1, b2, b3, bufo + boff[p] + ks * 32);
                mma_bf16(acc[0][2 * p],     a0, b0, b1);
                mma_bf16(acc[0][2 * p + 1], a0, b2, b3);
                mma_bf16(acc[1][2 * p],     a1, b0, b1);
                mma_bf16(acc[1][2 * p + 1], a1, b2, b3);
            }
        }

        if ((s % STG_PER_PH) == STG_PER_PH - 1) {
            const int ph = s / STG_PER_PH;
            const int cbase = ph * BN + nwarp * 64 + (lane & 3) * 2;
            #pragma unroll
            for (int nt = 0; nt < 8; ++nt) {
                const int col0 = cbase + nt * 8;
                const float c2a = s_c2[col0], c2b = s_c2[col0 + 1];
                #pragma unroll
                for (int mt = 0; mt < 2; ++mt) {
                    const float* a = acc[mt][nt];
                    const int r0 = mt * 2, r1 = mt * 2 + 1;
                    float s0 = fmaf(-2.f, a[0], c2a);
                    float s1 = fmaf(-2.f, a[1], c2b);
                    float s2 = fmaf(-2.f, a[2], c2a);
                    float s3 = fmaf(-2.f, a[3], c2b);
                    if (s0 < bv[r0]) { sv[r0] = bv[r0]; bv[r0] = s0; bi[r0] = col0; }
                    else if (s0 < sv[r0]) sv[r0] = s0;
                    if (s1 < bv[r0]) { sv[r0] = bv[r0]; bv[r0] = s1; bi[r0] = col0 + 1; }
                    else if (s1 < sv[r0]) sv[r0] = s1;
                    if (s2 < bv[r1]) { sv[r1] = bv[r1]; bv[r1] = s2; bi[r1] = col0; }
                    else if (s2 < sv[r1]) sv[r1] = s2;
                    if (s3 < bv[r1]) { sv[r1] = bv[r1]; bv[r1] = s3; bi[r1] = col0 + 1; }
                    else if (s3 < sv[r1]) sv[r1] = s3;
                }
            }
        }
    }

    // quad reduction (4 lanes sharing each row within the warp)
    #pragma unroll
    for (int r = 0; r < 4; ++r) {
        #pragma unroll
        for (int off = 1; off <= 2; off <<= 1) {
            float ov = __shfl_xor_sync(0xffffffffu, bv[r], off);
            float os = __shfl_xor_sync(0xffffffffu, sv[r], off);
            int   oi = __shfl_xor_sync(0xffffffffu, bi[r], off);
            if (ov < bv[r] || (ov == bv[r] && oi < bi[r])) {
                sv[r] = fminf(bv[r], os); bv[r] = ov; bi[r] = oi;
            } else {
                sv[r] = fminf(sv[r], ov);
            }
        }
    }
    __syncthreads();
    if ((lane & 3) == 0) {
        #pragma unroll
        for (int r = 0; r < 4; ++r) {
            int rowloc = mwarp * 32 + (lane >> 2) + r * 8;   // 0..127
            s_pbv[nwarp * 128 + rowloc] = bv[r];
            s_psv[nwarp * 128 + rowloc] = sv[r];
            s_pbi[nwarp * 128 + rowloc] = bi[r];
        }
    }
    __syncthreads();
    if (tid < BM) {
        float fb = s_pbv[tid], fs = s_psv[tid];
        int   fi = s_pbi[tid];
        #pragma unroll
        for (int t = 1; t < 4; ++t) {
            float ob = s_pbv[t * 128 + tid], os = s_psv[t * 128 + tid];
            int   oi = s_pbi[t * 128 + tid];
            if (ob < fb || (ob == fb && oi < fi)) {
                fs = fminf(fb, os); fb = ob; fi = oi;
            } else {
                fs = fminf(fs, ob);
            }
        }
        int row = rowbase + tid;
        g_best[row] = fi;
        if (fs - fb < TAU) {
            int slot = atomicAdd(&g_flag_count, 1);
            if (slot < CAP) g_flag_rows[slot] = row;
        }
    }
}

// ================= pass 2: fp64 rescue (proven) =================
__global__ __launch_bounds__(256) void rescue_kernel(
    const float* __restrict__ x,
    const float* __restrict__ cb)
{
    __shared__ float sx[D];
    __shared__ float wv[8];
    __shared__ int   wi[8];

    const int tid  = threadIdx.x;
    const int wid  = tid >> 5;
    const int lane = tid & 31;
    int total = g_flag_count;
    if (total > CAP) total = CAP;

    for (int f = blockIdx.x; f < total; f += gridDim.x) {
        const int row = g_flag_rows[f];
        for (int i = tid; i < D; i += 256) sx[i] = x[(size_t)row * D + i];
        __syncthreads();

        double x2 = 0.0;
        for (int e = lane; e < D; e += 32) { double v = (double)sx[e]; x2 += v * v; }
        #pragma unroll
        for (int o = 16; o; o >>= 1) x2 += __shfl_xor_sync(0xffffffffu, x2, o);
        const float x2f = (float)x2;

        float bv = FLT_MAX;
        int   bi = 1 << 30;
        for (int cw = wid; cw < KCB; cw += 8) {
            const float* c = cb + (size_t)cw * D;
            double dot = 0.0;
            for (int e = lane; e < D; e += 32)
                dot += (double)sx[e] * (double)c[e];
            #pragma unroll
            for (int o = 16; o; o >>= 1) dot += __shfl_xor_sync(0xffffffffu, dot, o);
            float d2 = (x2f - 2.0f * (float)dot) + g_c2[cw];
            if (d2 < bv) { bv = d2; bi = cw; }
        }
        if (lane == 0) { wv[wid] = bv; wi[wid] = bi; }
        __syncthreads();
        if (tid == 0) {
            float fbv = wv[0]; int fbi = wi[0];
            #pragma unroll
            for (int t = 1; t < 8; ++t)
                if (wv[t] < fbv || (wv[t] == fbv && wi[t] < fbi)) { fbv = wv[t]; fbi = wi[t]; }
            g_best[row] = fbi;
        }
        __syncthreads();
    }
}

// ================= pass 3: gather (warp per row) =================
__global__ __launch_bounds__(256) void gather_kernel(
    const float* __restrict__ cb,
    float* __restrict__ out)
{
    const int row  = blockIdx.x * 8 + (threadIdx.x >> 5);
    const int lane = threadIdx.x & 31;
    const int bi   = g_best[row];
    const float4* src = reinterpret_cast<const float4*>(cb + (size_t)bi * D);
    float4* dst = reinterpret_cast<float4*>(out + (size_t)row * D);
    #pragma unroll
    for (int i = 0; i < 4; ++i)
        dst[lane + i * 32] = src[lane + i * 32];
}

extern "C" void kernel_launch(void* const* d_in, const int* in_sizes, int n_in,
                              void* d_out, int out_size) {
    const float* x  = (const float*)d_in[0];   // [65536, 512]
    const float* cb = (const float*)d_in[1];   // [1024, 512]
    float* out = (float*)d_out;
    int nrows = in_sizes[0] / D;               // 65536

    cudaFuncSetAttribute(vq_mma_kernel,
                         cudaFuncAttributeMaxDynamicSharedMemorySize, SM_TOTAL);

    prep_x<<<(int)((size_t)nrows * D / 4 / 512), 512>>>(x);
    prep_cb<<<KCB * D / 4 / 512, 512>>>(cb);
    c2_kernel<<<KCB / 8, 256>>>(cb);
    vq_mma_kernel<<<nrows / BM, NTH, SM_TOTAL>>>();
    rescue_kernel<<<296, 256>>>(x, cb);
    gather_kernel<<<nrows / 8, 256>>>(cb, out);
}

// round 9
// speedup vs baseline: 10.2277x; 3.1164x over previous
#include <cuda_runtime.h>
#include <cuda_bf16.h>
#include <cfloat>
#include <cstdint>

#define D        512
#define KCB      1024
#define NROWS    65536
#define MARGIN   1.5f
#define CAP      65536
#define MAXCAND  12

#define BM       128            // rows per CTA
#define BN       256            // codewords per phase
#define NPH      4              // 1024 / 256
#define KC       128            // K elems per stage
#define NSTG     (NPH * (D / KC))   // 16
#define NTH      512

// smem layout (bytes)
#define SM_C2    0               // float[1024]
#define SM_BUF   4096
#define STRIDE_B 272             // 256B data + 16B pad -> conflict-free ldmatrix
#define A_BYTES  (BM * STRIDE_B)          // 34816
#define B_BYTES  (BN * STRIDE_B)          // 69632
#define BUF_BYTES (A_BYTES + B_BYTES)     // 104448
#define SM_TOTAL (SM_BUF + 2 * BUF_BYTES) // 212992

// ---- device scratch (no cudaMalloc allowed) ----
__device__ __nv_bfloat16 g_xhi[(size_t)NROWS * D];   // 64 MB
__device__ __nv_bfloat16 g_cbhi[KCB * D];            // 1 MB
__device__ float g_d2[(size_t)NROWS * KCB];          // 256 MB approx distances
__device__ float g_c2[KCB];
__device__ int   g_best[NROWS];
__device__ int   g_flag_rows[CAP];
__device__ int   g_flag_count;

// ================= PTX helpers (baseline sm_80 features only) =================
__device__ __forceinline__ uint32_t smem_u32(const void* p) {
    uint32_t a;
    asm("{ .reg .u64 t; cvta.to.shared.u64 t, %1; cvt.u32.u64 %0, t; }" : "=r"(a) : "l"(p));
    return a;
}
#define CP16(s, g)   asm volatile("cp.async.ca.shared.global [%0], [%1], 16;" :: "r"(s), "l"(g))
#define CPCOMMIT()   asm volatile("cp.async.commit_group;")
#define CPWAIT0()    asm volatile("cp.async.wait_group 0;")
#define LDSM4(r0, r1, r2, r3, a) \
    asm volatile("ldmatrix.sync.aligned.m8n8.x4.shared.b16 {%0,%1,%2,%3}, [%4];" \
                 : "=r"(r0), "=r"(r1), "=r"(r2), "=r"(r3) : "r"(a))

__device__ __forceinline__ void mma_bf16(float* c, const uint32_t* a, uint32_t b0, uint32_t b1) {
    asm volatile(
        "mma.sync.aligned.m16n8k16.row.col.f32.bf16.bf16.f32 "
        "{%0,%1,%2,%3}, {%4,%5,%6,%7}, {%8,%9}, {%0,%1,%2,%3};"
        : "+f"(c[0]), "+f"(c[1]), "+f"(c[2]), "+f"(c[3])
        : "r"(a[0]), "r"(a[1]), "r"(a[2]), "r"(a[3]), "r"(b0), "r"(b1));
}

// ================= prep: f32 -> bf16 hi =================
__global__ __launch_bounds__(512) void prep_x(const float* __restrict__ x) {
    size_t i = (size_t)blockIdx.x * 512 + threadIdx.x;     // over float4s
    float4 v = reinterpret_cast<const float4*>(x)[i];
    __nv_bfloat162 h01 = __floats2bfloat162_rn(v.x, v.y);
    __nv_bfloat162 h23 = __floats2bfloat162_rn(v.z, v.w);
    uint2 hw;
    hw.x = *reinterpret_cast<uint32_t*>(&h01); hw.y = *reinterpret_cast<uint32_t*>(&h23);
    reinterpret_cast<uint2*>(g_xhi)[i] = hw;
}
__global__ __launch_bounds__(512) void prep_cb(const float* __restrict__ cb) {
    size_t i = (size_t)blockIdx.x * 512 + threadIdx.x;
    float4 v = reinterpret_cast<const float4*>(cb)[i];
    __nv_bfloat162 h01 = __floats2bfloat162_rn(v.x, v.y);
    __nv_bfloat162 h23 = __floats2bfloat162_rn(v.z, v.w);
    uint2 hw;
    hw.x = *reinterpret_cast<uint32_t*>(&h01); hw.y = *reinterpret_cast<uint32_t*>(&h23);
    reinterpret_cast<uint2*>(g_cbhi)[i] = hw;
}

// ================= pass 0: ||c||^2 (fp64 accum) + reset flags =================
__global__ void c2_kernel(const float* __restrict__ cb) {
    if (blockIdx.x == 0 && threadIdx.x == 0) g_flag_count = 0;
    int cw   = blockIdx.x * (blockDim.x >> 5) + (threadIdx.x >> 5);
    int lane = threadIdx.x & 31;
    const float4* p = reinterpret_cast<const float4*>(cb + (size_t)cw * D);
    double s = 0.0;
    for (int t = lane; t < D / 4; t += 32) {
        float4 v = p[t];
        s += (double)v.x * v.x + (double)v.y * v.y + (double)v.z * v.z + (double)v.w * v.w;
    }
    #pragma unroll
    for (int o = 16; o; o >>= 1) s += __shfl_xor_sync(0xffffffffu, s, o);
    if (lane == 0) g_c2[cw] = (float)s;
}

// ================= pass A: hi*hi GEMM -> approx d2 matrix =================
__device__ __forceinline__ void stage_load(int s, int rowbase, uint32_t sbase, int tid) {
    const int ph = s >> 2;
    const int k0 = (s & 3) * KC;
    const uint32_t bufo = sbase + SM_BUF + (uint32_t)(s & 1) * BUF_BYTES;
    #pragma unroll
    for (int i = 0; i < 4; ++i) {                 // A: 128 rows x 16 chunks
        int id = tid + i * NTH;
        int row = id >> 4, kc = id & 15;
        CP16(bufo + row * STRIDE_B + kc * 16,
             g_xhi + (size_t)(rowbase + row) * D + k0 + kc * 8);
    }
    #pragma unroll
    for (int i = 0; i < 8; ++i) {                 // B: 256 rows x 16 chunks
        int id = tid + i * NTH;
        int n = id >> 4, kc = id & 15;
        CP16(bufo + A_BYTES + n * STRIDE_B + kc * 16,
             g_cbhi + (size_t)(ph * BN + n) * D + k0 + kc * 8);
    }
    CPCOMMIT();
}

__global__ __launch_bounds__(NTH, 1) void vq_gemm_kernel() {
    extern __shared__ char smem[];
    const uint32_t sbase = smem_u32(smem);
    const int tid   = threadIdx.x;
    const int lane  = tid & 31;
    const int wid   = tid >> 5;
    const int mwarp = wid >> 2;       // 0..3 -> 32 rows each
    const int nwarp = wid & 3;        // 0..3 -> 64 cols each
    const int rowbase = blockIdx.x * BM;

    float* s_c2 = reinterpret_cast<float*>(smem + SM_C2);
    for (int i = tid; i < KCB; i += NTH) s_c2[i] = g_c2[i];

    // per-thread ldmatrix offsets (within buffer)
    uint32_t aoff[2], boff[4];
    #pragma unroll
    for (int mt = 0; mt < 2; ++mt) {
        int row = mwarp * 32 + mt * 16 + (lane & 7) + ((lane >> 3) & 1) * 8;
        aoff[mt] = row * STRIDE_B + (lane >> 4) * 16;
    }
    #pragma unroll
    for (int p = 0; p < 4; ++p) {
        int n = nwarp * 64 + p * 16 + (lane & 7) + (lane >> 4) * 8;
        boff[p] = A_BYTES + n * STRIDE_B + ((lane >> 3) & 1) * 16;
    }

    float acc[2][8][4];

    stage_load(0, rowbase, sbase, tid);

    for (int s = 0; s < NSTG; ++s) {
        CPWAIT0();            // buf[s&1] fully staged
        __syncthreads();      // all warps done with compute(s-1)
        if (s + 1 < NSTG) stage_load(s + 1, rowbase, sbase, tid);

        if ((s & 3) == 0) {
            #pragma unroll
            for (int mt = 0; mt < 2; ++mt)
                #pragma unroll
                for (int nt = 0; nt < 8; ++nt)
                    #pragma unroll
                    for (int r = 0; r < 4; ++r) acc[mt][nt][r] = 0.f;
        }

        const uint32_t bufo = sbase + SM_BUF + (uint32_t)(s & 1) * BUF_BYTES;
        #pragma unroll
        for (int ks = 0; ks < 8; ++ks) {
            uint32_t a0[4], a1[4];
            LDSM4(a0[0], a0[1], a0[2], a0[3], bufo + aoff[0] + ks * 32);
            LDSM4(a1[0], a1[1], a1[2], a1[3], bufo + aoff[1] + ks * 32);
            #pragma unroll
            for (int p = 0; p < 4; ++p) {
                uint32_t b0, b1, b2, b3;
                LDSM4(b0, b1, b2, b3, bufo + boff[p] + ks * 32);
                mma_bf16(acc[0][2 * p],     a0, b0, b1);
                mma_bf16(acc[0][2 * p + 1], a0, b2, b3);
                mma_bf16(acc[1][2 * p],     a1, b0, b1);
                mma_bf16(acc[1][2 * p + 1], a1, b2, b3);
            }
        }

        if ((s & 3) == 3) {
            const int ph = s >> 2;
            const int cbase = ph * BN + nwarp * 64 + (lane & 3) * 2;
            #pragma unroll
            for (int mt = 0; mt < 2; ++mt) {
                const int row0 = rowbase + mwarp * 32 + mt * 16 + (lane >> 2);
                #pragma unroll
                for (int nt = 0; nt < 8; ++nt) {
                    const int col0 = cbase + nt * 8;
                    const float c2a = s_c2[col0], c2b = s_c2[col0 + 1];
                    const float* a = acc[mt][nt];
                    float2 v0 = { fmaf(-2.f, a[0], c2a), fmaf(-2.f, a[1], c2b) };
                    float2 v1 = { fmaf(-2.f, a[2], c2a), fmaf(-2.f, a[3], c2b) };
                    *reinterpret_cast<float2*>(&g_d2[(size_t)row0 * KCB + col0]) = v0;
                    *reinterpret_cast<float2*>(&g_d2[(size_t)(row0 + 8) * KCB + col0]) = v1;
                }
            }
        }
    }
}

// ================= pass B: per-row min + candidate rescore =================
__global__ __launch_bounds__(256) void select_kernel(
    const float* __restrict__ x,
    const float* __restrict__ cb)
{
    __shared__ int s_cand[8][MAXCAND];
    __shared__ int s_cnt[8];

    const int wid  = threadIdx.x >> 5;
    const int lane = threadIdx.x & 31;
    const int row  = blockIdx.x * 8 + wid;

    // load this row's 1024 approx distances (coalesced)
    const float* dr = g_d2 + (size_t)row * KCB;
    float vals[32];
    #pragma unroll
    for (int k = 0; k < 32; ++k) vals[k] = dr[lane + k * 32];

    // warp argmin (first-occurrence: tie -> lower index)
    float bv = vals[0]; int bi = lane;
    #pragma unroll
    for (int k = 1; k < 32; ++k) {
        int idx = lane + k * 32;
        if (vals[k] < bv || (vals[k] == bv && idx < bi)) { bv = vals[k]; bi = idx; }
    }
    #pragma unroll
    for (int o = 16; o; o >>= 1) {
        float ov = __shfl_xor_sync(0xffffffffu, bv, o);
        int   oi = __shfl_xor_sync(0xffffffffu, bi, o);
        if (ov < bv || (ov == bv && oi < bi)) { bv = ov; bi = oi; }
    }

    // collect candidates within margin
    if (lane == 0) s_cnt[wid] = 0;
    __syncwarp();
    const float thr = bv + MARGIN;
    #pragma unroll
    for (int k = 0; k < 32; ++k) {
        if (vals[k] < thr) {
            int slot = atomicAdd(&s_cnt[wid], 1);
            if (slot < MAXCAND) s_cand[wid][slot] = lane + k * 32;
        }
    }
    __syncwarp();
    const int cnt = s_cnt[wid];

    if (cnt <= 1) {                      // unambiguous winner
        if (lane == 0) g_best[row] = bi;
        return;
    }
    if (cnt > MAXCAND) {                 // rare overflow: full rescue later
        if (lane == 0) {
            g_best[row] = bi;
            int slot = atomicAdd(&g_flag_count, 1);
            if (slot < CAP) g_flag_rows[slot] = row;
        }
        return;
    }

    // exact rescore of candidates on the reference fp32 grid (fp64 dots)
    float xf[16];
    #pragma unroll
    for (int j = 0; j < 16; ++j) xf[j] = x[(size_t)row * D + lane + j * 32];
    double x2 = 0.0;
    #pragma unroll
    for (int j = 0; j < 16; ++j) x2 += (double)xf[j] * xf[j];
    #pragma unroll
    for (int o = 16; o; o >>= 1) x2 += __shfl_xor_sync(0xffffffffu, x2, o);
    const float x2f = (float)x2;

    float bvf = FLT_MAX; int bci = 1 << 30;
    for (int t = 0; t < cnt; ++t) {
        const int c = s_cand[wid][t];
        const float* cr = cb + (size_t)c * D;
        double dot = 0.0;
        #pragma unroll
        for (int j = 0; j < 16; ++j)
            dot += (double)xf[j] * (double)cr[lane + j * 32];
        #pragma unroll
        for (int o = 16; o; o >>= 1) dot += __shfl_xor_sync(0xffffffffu, dot, o);
        float d2 = (x2f - 2.0f * (float)dot) + g_c2[c];
        if (d2 < bvf || (d2 == bvf && c < bci)) { bvf = d2; bci = c; }
    }
    if (lane == 0) g_best[row] = bci;
}

// ================= rescue: full fp64 rescore for overflow rows =================
__global__ __launch_bounds__(256) void rescue_kernel(
    const float* __restrict__ x,
    const float* __restrict__ cb)
{
    __shared__ float sx[D];
    __shared__ float wv[8];
    __shared__ int   wi[8];

    const int tid  = threadIdx.x;
    const int wid  = tid >> 5;
    const int lane = tid & 31;
    int total = g_flag_count;
    if (total > CAP) total = CAP;

    for (int f = blockIdx.x; f < total; f += gridDim.x) {
        const int row = g_flag_rows[f];
        for (int i = tid; i < D; i += 256) sx[i] = x[(size_t)row * D + i];
        __syncthreads();

        double x2 = 0.0;
        for (int e = lane; e < D; e += 32) { double v = (double)sx[e]; x2 += v * v; }
        #pragma unroll
        for (int o = 16; o; o >>= 1) x2 += __shfl_xor_sync(0xffffffffu, x2, o);
        const float x2f = (float)x2;

        float bv = FLT_MAX;
        int   bi = 1 << 30;
        for (int cw = wid; cw < KCB; cw += 8) {
            const float* c = cb + (size_t)cw * D;
            double dot = 0.0;
            for (int e = lane; e < D; e += 32)
                dot += (double)sx[e] * (double)c[e];
            #pragma unroll
            for (int o = 16; o; o >>= 1) dot += __shfl_xor_sync(0xffffffffu, dot, o);
            float d2 = (x2f - 2.0f * (float)dot) + g_c2[cw];
            if (d2 < bv) { bv = d2; bi = cw; }
        }
        if (lane == 0) { wv[wid] = bv; wi[wid] = bi; }
        __syncthreads();
        if (tid == 0) {
            float fbv = wv[0]; int fbi = wi[0];
            #pragma unroll
            for (int t = 1; t < 8; ++t)
                if (wv[t] < fbv || (wv[t] == fbv && wi[t] < fbi)) { fbv = wv[t]; fbi = wi[t]; }
            g_best[row] = fbi;
        }
        __syncthreads();
    }
}

// ================= gather (warp per row) =================
__global__ __launch_bounds__(256) void gather_kernel(
    const float* __restrict__ cb,
    float* __restrict__ out)
{
    const int row  = blockIdx.x * 8 + (threadIdx.x >> 5);
    const int lane = threadIdx.x & 31;
    const int bi   = g_best[row];
    const float4* src = reinterpret_cast<const float4*>(cb + (size_t)bi * D);
    float4* dst = reinterpret_cast<float4*>(out + (size_t)row * D);
    #pragma unroll
    for (int i = 0; i < 4; ++i)
        dst[lane + i * 32] = src[lane + i * 32];
}

extern "C" void kernel_launch(void* const* d_in, const int* in_sizes, int n_in,
                              void* d_out, int out_size) {
    const float* x  = (const float*)d_in[0];   // [65536, 512]
    const float* cb = (const float*)d_in[1];   // [1024, 512]
    float* out = (float*)d_out;
    int nrows = in_sizes[0] / D;               // 65536

    cudaFuncSetAttribute(vq_gemm_kernel,
                         cudaFuncAttributeMaxDynamicSharedMemorySize, SM_TOTAL);

    prep_x<<<(int)((size_t)nrows * D / 4 / 512), 512>>>(x);
    prep_cb<<<KCB * D / 4 / 512, 512>>>(cb);
    c2_kernel<<<KCB / 8, 256>>>(cb);
    vq_gemm_kernel<<<nrows / BM, NTH, SM_TOTAL>>>();
    select_kernel<<<nrows / 8, 256>>>(x, cb);
    rescue_kernel<<<296, 256>>>(x, cb);
    gather_kernel<<<nrows / 8, 256>>>(cb, out);
}